// round 12
// baseline (speedup 1.0000x reference)
#include <cuda_runtime.h>
#include <cuda_fp16.h>
#include <math.h>
#include <stdint.h>

#define T_TOK 1024
#define HDIM  2048
#define NEXP  8
#define TOPK  2
#define IMOE  1408
#define ISH   5632
#define NPAIR (T_TOK*TOPK)

// ---------------- scratch (device globals; allocations forbidden) ----------------
__device__ __half g_x  [(size_t)T_TOK*HDIM];
__device__ __half g_hsh[(size_t)T_TOK*ISH];
__device__ __half g_xg [(size_t)NPAIR*HDIM];
__device__ __half g_he [(size_t)NPAIR*IMOE];
// fp16 weight scratch
__device__ __half g_wsgu[(size_t)2*ISH*HDIM];
__device__ __half g_wsdn[(size_t)HDIM*ISH];
__device__ __half g_w1  [(size_t)NEXP*2*IMOE*HDIM];
__device__ __half g_w2  [(size_t)NEXP*HDIM*IMOE];

__device__ float g_sgate[T_TOK];
__device__ int   g_top_i[T_TOK*TOPK];
__device__ float g_top_w[T_TOK*TOPK];
__device__ int   g_cnt[NEXP];
__device__ int   g_off[NEXP];
__device__ int   g_fill[NEXP];
__device__ int   g_pair_tok[NPAIR];
__device__ float g_pair_w[NPAIR];

// ---------------- ptx helpers (base sm_103-legal only) ----------------
__device__ __forceinline__ uint32_t smem_u32(const void* p) {
    uint32_t a;
    asm("{ .reg .u64 t; cvta.to.shared.u64 t, %1; cvt.u32.u64 %0, t; }" : "=r"(a) : "l"(p));
    return a;
}
#define LDMX4(r, addr) \
    asm volatile("ldmatrix.sync.aligned.m8n8.x4.shared.b16 {%0,%1,%2,%3}, [%4];" \
        : "=r"((r)[0]), "=r"((r)[1]), "=r"((r)[2]), "=r"((r)[3]) : "r"(addr))
#define MMA_F16(c, a, b0, b1) \
    asm volatile("mma.sync.aligned.m16n8k16.row.col.f32.f16.f16.f32 " \
        "{%0,%1,%2,%3}, {%4,%5,%6,%7}, {%8,%9}, {%0,%1,%2,%3};" \
        : "+f"((c)[0]), "+f"((c)[1]), "+f"((c)[2]), "+f"((c)[3]) \
        : "r"((a)[0]), "r"((a)[1]), "r"((a)[2]), "r"((a)[3]), "r"(b0), "r"(b1))
#define CP_ASYNC16(dst, src) \
    asm volatile("cp.async.cg.shared.global [%0], [%1], 16;" :: "r"(dst), "l"(src))
#define CP_COMMIT() asm volatile("cp.async.commit_group;")
#define CP_WAIT(n)  asm volatile("cp.async.wait_group %0;" :: "n"(n))

// ---------------- loaders (row stride 144B, conflict-free ldmatrix) ----------------
__device__ __forceinline__ void cp_tile64_clamp(uint32_t sdst, const __half* g,
                                                int rowadd, int rowmax, int ld, int k0, int tid) {
    size_t gg = __cvta_generic_to_global(g);
    #pragma unroll
    for (int i = 0; i < 2; i++) {
        int chunk = tid + i*256;
        int row = chunk >> 3, c8 = chunk & 7;
        int gr = min(rowadd + row, rowmax);
        CP_ASYNC16(sdst + row*144 + c8*16, gg + 2*((size_t)gr*ld + k0 + c8*8));
    }
}
__device__ __forceinline__ void cp_tile64(uint32_t sdst, const __half* g,
                                          int row0, int ld, int k0, int tid) {
    size_t gg = __cvta_generic_to_global(g);
    #pragma unroll
    for (int i = 0; i < 2; i++) {
        int chunk = tid + i*256;
        int row = chunk >> 3, c8 = chunk & 7;
        CP_ASYNC16(sdst + row*144 + c8*16, gg + 2*((size_t)(row0 + row)*ld + k0 + c8*8));
    }
}
__device__ __forceinline__ void cp_tile128(uint32_t sdst, const __half* g,
                                           int row0, int ld, int k0, int tid) {
    size_t gg = __cvta_generic_to_global(g);
    #pragma unroll
    for (int i = 0; i < 4; i++) {
        int chunk = tid + i*256;
        int row = chunk >> 3, c8 = chunk & 7;
        CP_ASYNC16(sdst + row*144 + c8*16, gg + 2*((size_t)(row0 + row)*ld + k0 + c8*8));
    }
}

#define BK 64
#define TILE64   9216           // 64*144
#define TILE128  18432          // 128*144
#define STAGE_GU  (3*TILE64)
#define SMEM_GU   (3*STAGE_GU)              // 82944 -> 2 CTAs/SM
#define STAGE_DN  (TILE64 + TILE128)
#define SMEM_DN   (3*STAGE_DN)              // 82944 -> 2 CTAs/SM

__device__ __forceinline__ float silu_f(float v) { return v / (1.f + expf(-v)); }

// ============ paired gate_up GEMM (64 rows x 64 gate-cols + 64 up-cols) ============
template<bool EXPERT>
__global__ __launch_bounds__(256, 2) void gemm_gu(
    const __half* __restrict__ A,
    const __half* __restrict__ W,
    __half* __restrict__ H,
    int K, int Nhalf)
{
    extern __shared__ char smem[];
    int tid = threadIdx.x;
    int bm = blockIdx.x * 64;
    int cnt = T_TOK, segoff = 0;
    if (EXPERT) {
        int e = blockIdx.z;
        cnt = g_cnt[e]; segoff = g_off[e];
        if (bm >= cnt) return;
        W += (size_t)e * (size_t)(2*Nhalf) * (size_t)K;
    }
    int bn = blockIdx.y * 64;
    uint32_t sbase = smem_u32(smem);
    int rowA = segoff + bm, rowAmax = segoff + cnt - 1;
    int NC = K / BK;

    auto load_stage = [&](int c) {
        uint32_t tb = sbase + (c % 3) * STAGE_GU;
        int k0 = c * BK;
        cp_tile64_clamp(tb,      A, rowA, rowAmax, K, k0, tid);
        cp_tile64(tb +   TILE64, W, bn,         K, k0, tid);
        cp_tile64(tb + 2*TILE64, W, Nhalf + bn, K, k0, tid);
        CP_COMMIT();
    };
    load_stage(0);
    if (NC > 1) load_stage(1);

    int lane = tid & 31, wid = tid >> 5;
    int wm = (wid >> 1) * 16, wn = (wid & 1) * 32;
    int lrow = lane & 15;
    int lcolb = (lane >> 4) * 16;

    float accg[4][4] = {}, accu[4][4] = {};

    for (int c = 0; c < NC; c++) {
        if (c + 2 < NC) { load_stage(c + 2); CP_WAIT(2); }
        else if (c + 1 < NC) { CP_WAIT(1); }
        else { CP_WAIT(0); }
        __syncthreads();

        uint32_t tb = sbase + (c % 3) * STAGE_GU;
        uint32_t sA = tb;
        uint32_t sG = tb + TILE64, sU = tb + 2*TILE64;

        #pragma unroll
        for (int kt = 0; kt < 4; kt++) {
            uint32_t cb = kt*32 + lcolb;
            uint32_t a[4];
            LDMX4(a, sA + (uint32_t)(wm + lrow)*144 + cb);
            {
                uint32_t b[2][4];
                #pragma unroll
                for (int p = 0; p < 2; p++)
                    LDMX4(b[p], sG + (uint32_t)(wn + p*16 + lrow)*144 + cb);
                #pragma unroll
                for (int nt = 0; nt < 4; nt++) {
                    int p = nt >> 1, s = nt & 1;
                    MMA_F16(accg[nt], a, b[p][s], b[p][s+2]);
                }
            }
            {
                uint32_t b[2][4];
                #pragma unroll
                for (int p = 0; p < 2; p++)
                    LDMX4(b[p], sU + (uint32_t)(wn + p*16 + lrow)*144 + cb);
                #pragma unroll
                for (int nt = 0; nt < 4; nt++) {
                    int p = nt >> 1, s = nt & 1;
                    MMA_F16(accu[nt], a, b[p][s], b[p][s+2]);
                }
            }
        }
        __syncthreads();
    }

    // fused epilogue: h = silu(g)*u -> fp16, direct store
    int groupID = lane >> 2, qid = lane & 3;
    #pragma unroll
    for (int half = 0; half < 2; half++) {
        int r = wm + groupID + half*8;
        if (bm + r >= cnt) continue;
        size_t rowoff = (size_t)(segoff + bm + r) * (size_t)Nhalf;
        #pragma unroll
        for (int nt = 0; nt < 4; nt++) {
            int col = bn + wn + nt*8 + qid*2;
            float h0 = silu_f(accg[nt][half*2+0]) * accu[nt][half*2+0];
            float h1 = silu_f(accg[nt][half*2+1]) * accu[nt][half*2+1];
            *(__half2*)&H[rowoff + col] = __halves2half2(__float2half_rn(h0), __float2half_rn(h1));
        }
    }
}

// ============ down GEMM, 64x128 tile ============
// MODE 0: out[row] = sgate[row]*acc (dense write). MODE 1: atomicAdd(out[tok], pair_w*acc)
template<int MODE>
__global__ __launch_bounds__(256, 2) void gemm_down(
    const __half* __restrict__ A,
    const __half* __restrict__ W,
    float* __restrict__ out, int K)
{
    extern __shared__ char smem[];
    int tid = threadIdx.x;
    int bm = blockIdx.x * 64;
    int cnt = T_TOK, segoff = 0;
    if (MODE == 1) {
        int e = blockIdx.z;
        cnt = g_cnt[e]; segoff = g_off[e];
        if (bm >= cnt) return;
        W += (size_t)e * (size_t)HDIM * (size_t)K;
    }
    int bn = blockIdx.y * 128;
    uint32_t sbase = smem_u32(smem);
    int rowA = segoff + bm, rowAmax = segoff + cnt - 1;
    int NC = K / BK;

    auto load_stage = [&](int c) {
        uint32_t tb = sbase + (c % 3) * STAGE_DN;
        int k0 = c * BK;
        cp_tile64_clamp(tb, A, rowA, rowAmax, K, k0, tid);
        cp_tile128(tb + TILE64, W, bn, K, k0, tid);
        CP_COMMIT();
    };
    load_stage(0);
    if (NC > 1) load_stage(1);

    int lane = tid & 31, wid = tid >> 5;
    int wm = (wid >> 2) * 32, wn = (wid & 3) * 32;
    int lrow = lane & 15;
    int lcolb = (lane >> 4) * 16;

    float acc[2][4][4] = {};

    for (int c = 0; c < NC; c++) {
        if (c + 2 < NC) { load_stage(c + 2); CP_WAIT(2); }
        else if (c + 1 < NC) { CP_WAIT(1); }
        else { CP_WAIT(0); }
        __syncthreads();

        uint32_t tb = sbase + (c % 3) * STAGE_DN;
        uint32_t sA = tb;
        uint32_t sB = tb + TILE64;

        #pragma unroll
        for (int kt = 0; kt < 4; kt++) {
            uint32_t cb = kt*32 + lcolb;
            uint32_t a[2][4], b[2][4];
            #pragma unroll
            for (int mt = 0; mt < 2; mt++)
                LDMX4(a[mt], sA + (uint32_t)(wm + mt*16 + lrow)*144 + cb);
            #pragma unroll
            for (int p = 0; p < 2; p++)
                LDMX4(b[p], sB + (uint32_t)(wn + p*16 + lrow)*144 + cb);
            #pragma unroll
            for (int mt = 0; mt < 2; mt++)
                #pragma unroll
                for (int nt = 0; nt < 4; nt++) {
                    int p = nt >> 1, s = nt & 1;
                    MMA_F16(acc[mt][nt], a[mt], b[p][s], b[p][s+2]);
                }
        }
        __syncthreads();
    }

    int groupID = lane >> 2, qid = lane & 3;
    #pragma unroll
    for (int mt = 0; mt < 2; mt++) {
        #pragma unroll
        for (int half = 0; half < 2; half++) {
            int lr = bm + wm + mt*16 + groupID + half*8;
            if (lr >= cnt) continue;
            #pragma unroll
            for (int nt = 0; nt < 4; nt++) {
                int col = bn + wn + nt*8 + qid*2;
                float v0 = acc[mt][nt][half*2 + 0];
                float v1 = acc[mt][nt][half*2 + 1];
                if (MODE == 0) {
                    float s = g_sgate[lr];
                    *(float2*)&out[(size_t)lr*HDIM + col] = make_float2(s*v0, s*v1);
                } else {
                    int p = segoff + lr;
                    int tok = g_pair_tok[p];
                    float w = g_pair_w[p];
                    atomicAdd(&out[(size_t)tok*HDIM + col],     w*v0);
                    atomicAdd(&out[(size_t)tok*HDIM + col + 1], w*v1);
                }
            }
        }
    }
}

// ---------------- conversion kernels ----------------
__global__ void cvt_kernel(const float* __restrict__ src, __half* __restrict__ dst, long n4) {
    long i = blockIdx.x*(long)blockDim.x + threadIdx.x;
    if (i >= n4) return;
    float4 v = ((const float4*)src)[i];
    __half2* D = (__half2*)(dst + 4*i);
    D[0] = __halves2half2(__float2half_rn(v.x), __float2half_rn(v.y));
    D[1] = __halves2half2(__float2half_rn(v.z), __float2half_rn(v.w));
}

__global__ void gather_cvt_kernel(const float* __restrict__ x) {
    int i = blockIdx.x*blockDim.x + threadIdx.x;
    const int n4 = NPAIR * (HDIM/4);
    if (i >= n4) return;
    int p = i / (HDIM/4), c4 = i % (HDIM/4);
    int tok = g_pair_tok[p];
    float4 v = *(const float4*)(x + (size_t)tok*HDIM + c4*4);
    size_t o = (size_t)p*HDIM + c4*4;
    ((__half2*)(g_xg + o))[0] = __halves2half2(__float2half_rn(v.x), __float2half_rn(v.y));
    ((__half2*)(g_xg + o))[1] = __halves2half2(__float2half_rn(v.z), __float2half_rn(v.w));
}

// ---------------- router ----------------
__global__ void zero_kernel() {
    int i = threadIdx.x;
    if (i < NEXP) { g_cnt[i] = 0; g_fill[i] = 0; }
}
__global__ void router_kernel(const float* __restrict__ x,
                              const float* __restrict__ gate_w,
                              const float* __restrict__ sgate_w) {
    int t = blockIdx.x;
    int w = threadIdx.x >> 5, lane = threadIdx.x & 31;
    __shared__ float logits[9];
    const float* xr = x + (size_t)t * HDIM;
    const float* wr = (w < 8) ? (gate_w + (size_t)w * HDIM) : sgate_w;
    float s = 0.f;
    for (int k = lane; k < HDIM; k += 32) s += xr[k] * wr[k];
    #pragma unroll
    for (int o = 16; o; o >>= 1) s += __shfl_xor_sync(0xffffffffu, s, o);
    if (lane == 0) logits[w] = s;
    __syncthreads();
    if (threadIdx.x == 0) {
        float mx = logits[0];
        #pragma unroll
        for (int e = 1; e < NEXP; e++) mx = fmaxf(mx, logits[e]);
        float p[NEXP], sum = 0.f;
        #pragma unroll
        for (int e = 0; e < NEXP; e++) { p[e] = expf(logits[e] - mx); sum += p[e]; }
        #pragma unroll
        for (int e = 0; e < NEXP; e++) p[e] /= sum;
        int i0 = 0; float v0 = p[0];
        #pragma unroll
        for (int e = 1; e < NEXP; e++) if (p[e] > v0) { v0 = p[e]; i0 = e; }
        int i1 = -1; float v1 = -1.f;
        #pragma unroll
        for (int e = 0; e < NEXP; e++) if (e != i0 && p[e] > v1) { v1 = p[e]; i1 = e; }
        float inv = 1.f / (v0 + v1);
        g_top_i[t*2+0] = i0; g_top_w[t*2+0] = v0 * inv;
        g_top_i[t*2+1] = i1; g_top_w[t*2+1] = v1 * inv;
        atomicAdd(&g_cnt[i0], 1);
        atomicAdd(&g_cnt[i1], 1);
        g_sgate[t] = 1.f / (1.f + expf(-logits[8]));
    }
}
__global__ void scan_kernel() {
    if (threadIdx.x == 0) {
        int o = 0;
        for (int e = 0; e < NEXP; e++) { g_off[e] = o; o += g_cnt[e]; }
    }
}
__global__ void scatter_kernel() {
    int t = blockIdx.x * blockDim.x + threadIdx.x;
    if (t >= T_TOK) return;
    #pragma unroll
    for (int k = 0; k < TOPK; k++) {
        int e = g_top_i[t*2+k];
        int pos = g_off[e] + atomicAdd(&g_fill[e], 1);
        g_pair_tok[pos] = t;
        g_pair_w[pos]   = g_top_w[t*2+k];
    }
}

// ---------------- launch ----------------
static void* sym(const void* s) { void* p = nullptr; cudaGetSymbolAddress(&p, s); return p; }

extern "C" void kernel_launch(void* const* d_in, const int* in_sizes, int n_in,
                              void* d_out, int out_size) {
    const float* x     = (const float*)d_in[0];
    const float* gatew = (const float*)d_in[1];
    const float* w1    = (const float*)d_in[2];
    const float* w2    = (const float*)d_in[3];
    const float* sgu   = (const float*)d_in[4];
    const float* sdown = (const float*)d_in[5];
    const float* sgw   = (const float*)d_in[6];
    float* out = (float*)d_out;

    cudaFuncSetAttribute(gemm_gu<false>, cudaFuncAttributeMaxDynamicSharedMemorySize, SMEM_GU);
    cudaFuncSetAttribute(gemm_gu<true>,  cudaFuncAttributeMaxDynamicSharedMemorySize, SMEM_GU);
    cudaFuncSetAttribute(gemm_down<0>,   cudaFuncAttributeMaxDynamicSharedMemorySize, SMEM_DN);
    cudaFuncSetAttribute(gemm_down<1>,   cudaFuncAttributeMaxDynamicSharedMemorySize, SMEM_DN);

    __half *xh  = (__half*)sym(g_x);
    __half *hsh = (__half*)sym(g_hsh);
    __half *xgh = (__half*)sym(g_xg);
    __half *heh = (__half*)sym(g_he);
    __half *wsgu= (__half*)sym(g_wsgu);
    __half *wsdn= (__half*)sym(g_wsdn);
    __half *w1h = (__half*)sym(g_w1);
    __half *w2h = (__half*)sym(g_w2);

    // Per-call streams/events (no static state, no device allocations).
    cudaStream_t s2, s3;
    cudaEvent_t e_fork, e_w1, e_sd, e_w2, e_he, e_done2;
    cudaStreamCreateWithFlags(&s2, cudaStreamNonBlocking);
    cudaStreamCreateWithFlags(&s3, cudaStreamNonBlocking);
    cudaEventCreateWithFlags(&e_fork,  cudaEventDisableTiming);
    cudaEventCreateWithFlags(&e_w1,    cudaEventDisableTiming);
    cudaEventCreateWithFlags(&e_sd,    cudaEventDisableTiming);
    cudaEventCreateWithFlags(&e_w2,    cudaEventDisableTiming);
    cudaEventCreateWithFlags(&e_he,    cudaEventDisableTiming);
    cudaEventCreateWithFlags(&e_done2, cudaEventDisableTiming);

    cudaEventRecord(e_fork, 0);
    cudaStreamWaitEvent(s2, e_fork, 0);
    cudaStreamWaitEvent(s3, e_fork, 0);

    auto cvt = [](cudaStream_t st, const float* s, __half* d, long n) {
        long n4 = n / 4;
        cvt_kernel<<<(unsigned)((n4 + 255) / 256), 256, 0, st>>>(s, d, n4);
    };

    // --- s3: all weight cvts, in need-order (w1 first: expert gu gate) ---
    cvt(s3, w1, w1h, (long)NEXP*2*IMOE*HDIM);
    cudaEventRecord(e_w1, s3);
    cvt(s3, sdown, wsdn, (long)HDIM*ISH);
    cudaEventRecord(e_sd, s3);
    cvt(s3, w2, w2h, (long)NEXP*HDIM*IMOE);
    cudaEventRecord(e_w2, s3);

    // --- s2: router chain (concurrent with w1 cvt) -> expert gu ---
    zero_kernel<<<1, 32, 0, s2>>>();
    router_kernel<<<T_TOK, 288, 0, s2>>>(x, gatew, sgw);
    scan_kernel<<<1, 32, 0, s2>>>();
    scatter_kernel<<<(T_TOK + 255) / 256, 256, 0, s2>>>();
    gather_cvt_kernel<<<(NPAIR*(HDIM/4) + 255) / 256, 256, 0, s2>>>(x);
    cudaStreamWaitEvent(s2, e_w1, 0);
    gemm_gu<true><<<dim3(T_TOK/64, IMOE/64, NEXP), 256, SMEM_GU, s2>>>(
        xgh, w1h, heh, HDIM, IMOE);
    cudaEventRecord(e_he, s2);

    // --- default stream: shared chain, then expert down (dense write precedes atomics) ---
    cvt(0, x, xh, (long)T_TOK*HDIM);
    cvt(0, sgu, wsgu, (long)2*ISH*HDIM);
    gemm_gu<false><<<dim3(T_TOK/64, ISH/64), 256, SMEM_GU>>>(
        xh, wsgu, hsh, HDIM, ISH);
    cudaStreamWaitEvent(0, e_sd, 0);
    gemm_down<0><<<dim3(T_TOK/64, HDIM/128), 256, SMEM_DN>>>(
        hsh, wsdn, out, ISH);
    cudaStreamWaitEvent(0, e_he, 0);
    cudaStreamWaitEvent(0, e_w2, 0);
    gemm_down<1><<<dim3(T_TOK/64, HDIM/128, NEXP), 256, SMEM_DN>>>(
        heh, w2h, out, IMOE);

    cudaEventDestroy(e_fork);
    cudaEventDestroy(e_w1);
    cudaEventDestroy(e_sd);
    cudaEventDestroy(e_w2);
    cudaEventDestroy(e_he);
    cudaEventDestroy(e_done2);
    cudaStreamDestroy(s2);
    cudaStreamDestroy(s3);
}

// round 13
// speedup vs baseline: 1.0230x; 1.0230x over previous
#include <cuda_runtime.h>
#include <cuda_fp16.h>
#include <math.h>
#include <stdint.h>

#define T_TOK 1024
#define HDIM  2048
#define NEXP  8
#define TOPK  2
#define IMOE  1408
#define ISH   5632
#define NPAIR (T_TOK*TOPK)

// ---------------- scratch (device globals; allocations forbidden) ----------------
__device__ __half g_x  [(size_t)T_TOK*HDIM];
__device__ __half g_hsh[(size_t)T_TOK*ISH];
__device__ __half g_xg [(size_t)NPAIR*HDIM];
__device__ __half g_he [(size_t)NPAIR*IMOE];
// fp16 weight scratch
__device__ __half g_wsgu[(size_t)2*ISH*HDIM];
__device__ __half g_wsdn[(size_t)HDIM*ISH];
__device__ __half g_w1  [(size_t)NEXP*2*IMOE*HDIM];
__device__ __half g_w2  [(size_t)NEXP*HDIM*IMOE];

__device__ float g_sgate[T_TOK];
__device__ int   g_top_i[T_TOK*TOPK];
__device__ float g_top_w[T_TOK*TOPK];
__device__ int   g_cnt[NEXP];
__device__ int   g_off[NEXP];
__device__ int   g_fill[NEXP];
__device__ int   g_pair_tok[NPAIR];
__device__ float g_pair_w[NPAIR];

// ---------------- ptx helpers (base sm_103-legal only) ----------------
__device__ __forceinline__ uint32_t smem_u32(const void* p) {
    uint32_t a;
    asm("{ .reg .u64 t; cvta.to.shared.u64 t, %1; cvt.u32.u64 %0, t; }" : "=r"(a) : "l"(p));
    return a;
}
#define LDMX4(r, addr) \
    asm volatile("ldmatrix.sync.aligned.m8n8.x4.shared.b16 {%0,%1,%2,%3}, [%4];" \
        : "=r"((r)[0]), "=r"((r)[1]), "=r"((r)[2]), "=r"((r)[3]) : "r"(addr))
#define MMA_F16(c, a, b0, b1) \
    asm volatile("mma.sync.aligned.m16n8k16.row.col.f32.f16.f16.f32 " \
        "{%0,%1,%2,%3}, {%4,%5,%6,%7}, {%8,%9}, {%0,%1,%2,%3};" \
        : "+f"((c)[0]), "+f"((c)[1]), "+f"((c)[2]), "+f"((c)[3]) \
        : "r"((a)[0]), "r"((a)[1]), "r"((a)[2]), "r"((a)[3]), "r"(b0), "r"(b1))
#define CP_ASYNC16(dst, src) \
    asm volatile("cp.async.cg.shared.global [%0], [%1], 16;" :: "r"(dst), "l"(src))
#define CP_COMMIT() asm volatile("cp.async.commit_group;")
#define CP_WAIT(n)  asm volatile("cp.async.wait_group %0;" :: "n"(n))

// ---------------- loaders (row stride 144B, conflict-free ldmatrix) ----------------
__device__ __forceinline__ void cp_tile64_clamp(uint32_t sdst, const __half* g,
                                                int rowadd, int rowmax, int ld, int k0, int tid) {
    size_t gg = __cvta_generic_to_global(g);
    #pragma unroll
    for (int i = 0; i < 2; i++) {
        int chunk = tid + i*256;
        int row = chunk >> 3, c8 = chunk & 7;
        int gr = min(rowadd + row, rowmax);
        CP_ASYNC16(sdst + row*144 + c8*16, gg + 2*((size_t)gr*ld + k0 + c8*8));
    }
}
__device__ __forceinline__ void cp_tile64(uint32_t sdst, const __half* g,
                                          int row0, int ld, int k0, int tid) {
    size_t gg = __cvta_generic_to_global(g);
    #pragma unroll
    for (int i = 0; i < 2; i++) {
        int chunk = tid + i*256;
        int row = chunk >> 3, c8 = chunk & 7;
        CP_ASYNC16(sdst + row*144 + c8*16, gg + 2*((size_t)(row0 + row)*ld + k0 + c8*8));
    }
}
__device__ __forceinline__ void cp_tile128(uint32_t sdst, const __half* g,
                                           int row0, int ld, int k0, int tid) {
    size_t gg = __cvta_generic_to_global(g);
    #pragma unroll
    for (int i = 0; i < 4; i++) {
        int chunk = tid + i*256;
        int row = chunk >> 3, c8 = chunk & 7;
        CP_ASYNC16(sdst + row*144 + c8*16, gg + 2*((size_t)(row0 + row)*ld + k0 + c8*8));
    }
}

#define BK 64
#define TILE64   9216           // 64*144
#define TILE128  18432          // 128*144
#define STAGE_GU  (3*TILE64)
#define SMEM_GU   (3*STAGE_GU)              // 82944 -> 2 CTAs/SM
#define STAGE_DN  (TILE64 + TILE128)
#define SMEM_DN   (3*STAGE_DN)              // 82944 -> 2 CTAs/SM

__device__ __forceinline__ float silu_f(float v) { return v / (1.f + expf(-v)); }

// ============ paired gate_up GEMM (64 rows x 64 gate-cols + 64 up-cols) ============
template<bool EXPERT>
__global__ __launch_bounds__(256, 2) void gemm_gu(
    const __half* __restrict__ A,
    const __half* __restrict__ W,
    __half* __restrict__ H,
    int K, int Nhalf)
{
    extern __shared__ char smem[];
    int tid = threadIdx.x;
    int bm = blockIdx.x * 64;
    int cnt = T_TOK, segoff = 0;
    if (EXPERT) {
        int e = blockIdx.z;
        cnt = g_cnt[e]; segoff = g_off[e];
        if (bm >= cnt) return;
        W += (size_t)e * (size_t)(2*Nhalf) * (size_t)K;
    }
    int bn = blockIdx.y * 64;
    uint32_t sbase = smem_u32(smem);
    int rowA = segoff + bm, rowAmax = segoff + cnt - 1;
    int NC = K / BK;

    auto load_stage = [&](int c) {
        uint32_t tb = sbase + (c % 3) * STAGE_GU;
        int k0 = c * BK;
        cp_tile64_clamp(tb,      A, rowA, rowAmax, K, k0, tid);
        cp_tile64(tb +   TILE64, W, bn,         K, k0, tid);
        cp_tile64(tb + 2*TILE64, W, Nhalf + bn, K, k0, tid);
        CP_COMMIT();
    };
    load_stage(0);
    if (NC > 1) load_stage(1);

    int lane = tid & 31, wid = tid >> 5;
    int wm = (wid >> 1) * 16, wn = (wid & 1) * 32;
    int lrow = lane & 15;
    int lcolb = (lane >> 4) * 16;

    float accg[4][4] = {}, accu[4][4] = {};

    for (int c = 0; c < NC; c++) {
        if (c + 2 < NC) { load_stage(c + 2); CP_WAIT(2); }
        else if (c + 1 < NC) { CP_WAIT(1); }
        else { CP_WAIT(0); }
        __syncthreads();

        uint32_t tb = sbase + (c % 3) * STAGE_GU;
        uint32_t sA = tb;
        uint32_t sG = tb + TILE64, sU = tb + 2*TILE64;

        #pragma unroll
        for (int kt = 0; kt < 4; kt++) {
            uint32_t cb = kt*32 + lcolb;
            uint32_t a[4];
            LDMX4(a, sA + (uint32_t)(wm + lrow)*144 + cb);
            {
                uint32_t b[2][4];
                #pragma unroll
                for (int p = 0; p < 2; p++)
                    LDMX4(b[p], sG + (uint32_t)(wn + p*16 + lrow)*144 + cb);
                #pragma unroll
                for (int nt = 0; nt < 4; nt++) {
                    int p = nt >> 1, s = nt & 1;
                    MMA_F16(accg[nt], a, b[p][s], b[p][s+2]);
                }
            }
            {
                uint32_t b[2][4];
                #pragma unroll
                for (int p = 0; p < 2; p++)
                    LDMX4(b[p], sU + (uint32_t)(wn + p*16 + lrow)*144 + cb);
                #pragma unroll
                for (int nt = 0; nt < 4; nt++) {
                    int p = nt >> 1, s = nt & 1;
                    MMA_F16(accu[nt], a, b[p][s], b[p][s+2]);
                }
            }
        }
        __syncthreads();
    }

    // fused epilogue: h = silu(g)*u -> fp16, direct store
    int groupID = lane >> 2, qid = lane & 3;
    #pragma unroll
    for (int half = 0; half < 2; half++) {
        int r = wm + groupID + half*8;
        if (bm + r >= cnt) continue;
        size_t rowoff = (size_t)(segoff + bm + r) * (size_t)Nhalf;
        #pragma unroll
        for (int nt = 0; nt < 4; nt++) {
            int col = bn + wn + nt*8 + qid*2;
            float h0 = silu_f(accg[nt][half*2+0]) * accu[nt][half*2+0];
            float h1 = silu_f(accg[nt][half*2+1]) * accu[nt][half*2+1];
            *(__half2*)&H[rowoff + col] = __halves2half2(__float2half_rn(h0), __float2half_rn(h1));
        }
    }
}

// ============ down GEMM, 64x128 tile ============
// MODE 0: out[row] = sgate[row]*acc (dense write). MODE 1: atomicAdd(out[tok], pair_w*acc)
template<int MODE>
__global__ __launch_bounds__(256, 2) void gemm_down(
    const __half* __restrict__ A,
    const __half* __restrict__ W,
    float* __restrict__ out, int K)
{
    extern __shared__ char smem[];
    int tid = threadIdx.x;
    int bm = blockIdx.x * 64;
    int cnt = T_TOK, segoff = 0;
    if (MODE == 1) {
        int e = blockIdx.z;
        cnt = g_cnt[e]; segoff = g_off[e];
        if (bm >= cnt) return;
        W += (size_t)e * (size_t)HDIM * (size_t)K;
    }
    int bn = blockIdx.y * 128;
    uint32_t sbase = smem_u32(smem);
    int rowA = segoff + bm, rowAmax = segoff + cnt - 1;
    int NC = K / BK;

    auto load_stage = [&](int c) {
        uint32_t tb = sbase + (c % 3) * STAGE_DN;
        int k0 = c * BK;
        cp_tile64_clamp(tb, A, rowA, rowAmax, K, k0, tid);
        cp_tile128(tb + TILE64, W, bn, K, k0, tid);
        CP_COMMIT();
    };
    load_stage(0);
    if (NC > 1) load_stage(1);

    int lane = tid & 31, wid = tid >> 5;
    int wm = (wid >> 2) * 32, wn = (wid & 3) * 32;
    int lrow = lane & 15;
    int lcolb = (lane >> 4) * 16;

    float acc[2][4][4] = {};

    for (int c = 0; c < NC; c++) {
        if (c + 2 < NC) { load_stage(c + 2); CP_WAIT(2); }
        else if (c + 1 < NC) { CP_WAIT(1); }
        else { CP_WAIT(0); }
        __syncthreads();

        uint32_t tb = sbase + (c % 3) * STAGE_DN;
        uint32_t sA = tb;
        uint32_t sB = tb + TILE64;

        #pragma unroll
        for (int kt = 0; kt < 4; kt++) {
            uint32_t cb = kt*32 + lcolb;
            uint32_t a[2][4], b[2][4];
            #pragma unroll
            for (int mt = 0; mt < 2; mt++)
                LDMX4(a[mt], sA + (uint32_t)(wm + mt*16 + lrow)*144 + cb);
            #pragma unroll
            for (int p = 0; p < 2; p++)
                LDMX4(b[p], sB + (uint32_t)(wn + p*16 + lrow)*144 + cb);
            #pragma unroll
            for (int mt = 0; mt < 2; mt++)
                #pragma unroll
                for (int nt = 0; nt < 4; nt++) {
                    int p = nt >> 1, s = nt & 1;
                    MMA_F16(acc[mt][nt], a[mt], b[p][s], b[p][s+2]);
                }
        }
        __syncthreads();
    }

    int groupID = lane >> 2, qid = lane & 3;
    #pragma unroll
    for (int mt = 0; mt < 2; mt++) {
        #pragma unroll
        for (int half = 0; half < 2; half++) {
            int lr = bm + wm + mt*16 + groupID + half*8;
            if (lr >= cnt) continue;
            #pragma unroll
            for (int nt = 0; nt < 4; nt++) {
                int col = bn + wn + nt*8 + qid*2;
                float v0 = acc[mt][nt][half*2 + 0];
                float v1 = acc[mt][nt][half*2 + 1];
                if (MODE == 0) {
                    float s = g_sgate[lr];
                    *(float2*)&out[(size_t)lr*HDIM + col] = make_float2(s*v0, s*v1);
                } else {
                    int p = segoff + lr;
                    int tok = g_pair_tok[p];
                    float w = g_pair_w[p];
                    atomicAdd(&out[(size_t)tok*HDIM + col],     w*v0);
                    atomicAdd(&out[(size_t)tok*HDIM + col + 1], w*v1);
                }
            }
        }
    }
}

// ---------------- conversion kernels ----------------
__global__ void cvt_kernel(const float* __restrict__ src, __half* __restrict__ dst, long n4) {
    long i = blockIdx.x*(long)blockDim.x + threadIdx.x;
    if (i >= n4) return;
    float4 v = ((const float4*)src)[i];
    __half2* D = (__half2*)(dst + 4*i);
    D[0] = __halves2half2(__float2half_rn(v.x), __float2half_rn(v.y));
    D[1] = __halves2half2(__float2half_rn(v.z), __float2half_rn(v.w));
}

__global__ void gather_cvt_kernel(const float* __restrict__ x) {
    int i = blockIdx.x*blockDim.x + threadIdx.x;
    const int n4 = NPAIR * (HDIM/4);
    if (i >= n4) return;
    int p = i / (HDIM/4), c4 = i % (HDIM/4);
    int tok = g_pair_tok[p];
    float4 v = *(const float4*)(x + (size_t)tok*HDIM + c4*4);
    size_t o = (size_t)p*HDIM + c4*4;
    ((__half2*)(g_xg + o))[0] = __halves2half2(__float2half_rn(v.x), __float2half_rn(v.y));
    ((__half2*)(g_xg + o))[1] = __halves2half2(__float2half_rn(v.z), __float2half_rn(v.w));
}

// ---------------- router ----------------
__global__ void zero_kernel() {
    int i = threadIdx.x;
    if (i < NEXP) { g_cnt[i] = 0; g_fill[i] = 0; }
}
__global__ void router_kernel(const float* __restrict__ x,
                              const float* __restrict__ gate_w,
                              const float* __restrict__ sgate_w) {
    int t = blockIdx.x;
    int w = threadIdx.x >> 5, lane = threadIdx.x & 31;
    __shared__ float logits[9];
    const float* xr = x + (size_t)t * HDIM;
    const float* wr = (w < 8) ? (gate_w + (size_t)w * HDIM) : sgate_w;
    float s = 0.f;
    for (int k = lane; k < HDIM; k += 32) s += xr[k] * wr[k];
    #pragma unroll
    for (int o = 16; o; o >>= 1) s += __shfl_xor_sync(0xffffffffu, s, o);
    if (lane == 0) logits[w] = s;
    __syncthreads();
    if (threadIdx.x == 0) {
        float mx = logits[0];
        #pragma unroll
        for (int e = 1; e < NEXP; e++) mx = fmaxf(mx, logits[e]);
        float p[NEXP], sum = 0.f;
        #pragma unroll
        for (int e = 0; e < NEXP; e++) { p[e] = expf(logits[e] - mx); sum += p[e]; }
        #pragma unroll
        for (int e = 0; e < NEXP; e++) p[e] /= sum;
        int i0 = 0; float v0 = p[0];
        #pragma unroll
        for (int e = 1; e < NEXP; e++) if (p[e] > v0) { v0 = p[e]; i0 = e; }
        int i1 = -1; float v1 = -1.f;
        #pragma unroll
        for (int e = 0; e < NEXP; e++) if (e != i0 && p[e] > v1) { v1 = p[e]; i1 = e; }
        float inv = 1.f / (v0 + v1);
        g_top_i[t*2+0] = i0; g_top_w[t*2+0] = v0 * inv;
        g_top_i[t*2+1] = i1; g_top_w[t*2+1] = v1 * inv;
        atomicAdd(&g_cnt[i0], 1);
        atomicAdd(&g_cnt[i1], 1);
        g_sgate[t] = 1.f / (1.f + expf(-logits[8]));
    }
}
__global__ void scan_kernel() {
    if (threadIdx.x == 0) {
        int o = 0;
        for (int e = 0; e < NEXP; e++) { g_off[e] = o; o += g_cnt[e]; }
    }
}
__global__ void scatter_kernel() {
    int t = blockIdx.x * blockDim.x + threadIdx.x;
    if (t >= T_TOK) return;
    #pragma unroll
    for (int k = 0; k < TOPK; k++) {
        int e = g_top_i[t*2+k];
        int pos = g_off[e] + atomicAdd(&g_fill[e], 1);
        g_pair_tok[pos] = t;
        g_pair_w[pos]   = g_top_w[t*2+k];
    }
}

// ---------------- launch ----------------
static void* sym(const void* s) { void* p = nullptr; cudaGetSymbolAddress(&p, s); return p; }

extern "C" void kernel_launch(void* const* d_in, const int* in_sizes, int n_in,
                              void* d_out, int out_size) {
    const float* x     = (const float*)d_in[0];
    const float* gatew = (const float*)d_in[1];
    const float* w1    = (const float*)d_in[2];
    const float* w2    = (const float*)d_in[3];
    const float* sgu   = (const float*)d_in[4];
    const float* sdown = (const float*)d_in[5];
    const float* sgw   = (const float*)d_in[6];
    float* out = (float*)d_out;

    cudaFuncSetAttribute(gemm_gu<false>, cudaFuncAttributeMaxDynamicSharedMemorySize, SMEM_GU);
    cudaFuncSetAttribute(gemm_gu<true>,  cudaFuncAttributeMaxDynamicSharedMemorySize, SMEM_GU);
    cudaFuncSetAttribute(gemm_down<0>,   cudaFuncAttributeMaxDynamicSharedMemorySize, SMEM_DN);
    cudaFuncSetAttribute(gemm_down<1>,   cudaFuncAttributeMaxDynamicSharedMemorySize, SMEM_DN);

    __half *xh  = (__half*)sym(g_x);
    __half *hsh = (__half*)sym(g_hsh);
    __half *xgh = (__half*)sym(g_xg);
    __half *heh = (__half*)sym(g_he);
    __half *wsgu= (__half*)sym(g_wsgu);
    __half *wsdn= (__half*)sym(g_wsdn);
    __half *w1h = (__half*)sym(g_w1);
    __half *w2h = (__half*)sym(g_w2);

    // Per-call streams/events (no static state, no device allocations).
    cudaStream_t s2;
    cudaEvent_t e_fork, e_sd, e_he, e_w2;
    cudaStreamCreateWithFlags(&s2, cudaStreamNonBlocking);
    cudaEventCreateWithFlags(&e_fork, cudaEventDisableTiming);
    cudaEventCreateWithFlags(&e_sd,   cudaEventDisableTiming);
    cudaEventCreateWithFlags(&e_he,   cudaEventDisableTiming);
    cudaEventCreateWithFlags(&e_w2,   cudaEventDisableTiming);

    cudaEventRecord(e_fork, 0);
    cudaStreamWaitEvent(s2, e_fork, 0);

    auto cvt = [](cudaStream_t st, const float* s, __half* d, long n) {
        long n4 = n / 4;
        cvt_kernel<<<(unsigned)((n4 + 255) / 256), 256, 0, st>>>(s, d, n4);
    };

    // --- s2: router chain -> w1 cvt -> sdown cvt -> expert gu -> w2 cvt ---
    zero_kernel<<<1, 32, 0, s2>>>();
    router_kernel<<<T_TOK, 288, 0, s2>>>(x, gatew, sgw);
    scan_kernel<<<1, 32, 0, s2>>>();
    scatter_kernel<<<(T_TOK + 255) / 256, 256, 0, s2>>>();
    gather_cvt_kernel<<<(NPAIR*(HDIM/4) + 255) / 256, 256, 0, s2>>>(x);
    cvt(s2, w1, w1h, (long)NEXP*2*IMOE*HDIM);
    cvt(s2, sdown, wsdn, (long)HDIM*ISH);
    cudaEventRecord(e_sd, s2);
    gemm_gu<true><<<dim3(T_TOK/64, IMOE/64, NEXP), 256, SMEM_GU, s2>>>(
        xgh, w1h, heh, HDIM, IMOE);
    cudaEventRecord(e_he, s2);
    cvt(s2, w2, w2h, (long)NEXP*HDIM*IMOE);
    cudaEventRecord(e_w2, s2);

    // --- default stream: shared chain (head = x+sgu cvt only), then expert down ---
    cvt(0, x, xh, (long)T_TOK*HDIM);
    cvt(0, sgu, wsgu, (long)2*ISH*HDIM);
    gemm_gu<false><<<dim3(T_TOK/64, ISH/64), 256, SMEM_GU>>>(
        xh, wsgu, hsh, HDIM, ISH);
    cudaStreamWaitEvent(0, e_sd, 0);
    gemm_down<0><<<dim3(T_TOK/64, HDIM/128), 256, SMEM_DN>>>(
        hsh, wsdn, out, ISH);
    cudaStreamWaitEvent(0, e_he, 0);
    cudaStreamWaitEvent(0, e_w2, 0);
    gemm_down<1><<<dim3(T_TOK/64, HDIM/128, NEXP), 256, SMEM_DN>>>(
        heh, w2h, out, IMOE);

    cudaEventDestroy(e_fork);
    cudaEventDestroy(e_sd);
    cudaEventDestroy(e_he);
    cudaEventDestroy(e_w2);
    cudaStreamDestroy(s2);
}

// round 14
// speedup vs baseline: 1.1080x; 1.0831x over previous
#include <cuda_runtime.h>
#include <cuda_fp16.h>
#include <math.h>
#include <stdint.h>

#define T_TOK 1024
#define HDIM  2048
#define NEXP  8
#define TOPK  2
#define IMOE  1408
#define ISH   5632
#define NPAIR (T_TOK*TOPK)

// ---------------- scratch (device globals; allocations forbidden) ----------------
__device__ __half g_x  [(size_t)T_TOK*HDIM];
__device__ __half g_hsh[(size_t)T_TOK*ISH];
__device__ __half g_xg [(size_t)NPAIR*HDIM];
__device__ __half g_he [(size_t)NPAIR*IMOE];
// fp16 weight scratch
__device__ __half g_wsgu[(size_t)2*ISH*HDIM];
__device__ __half g_wsdn[(size_t)HDIM*ISH];
__device__ __half g_w1  [(size_t)NEXP*2*IMOE*HDIM];
__device__ __half g_w2  [(size_t)NEXP*HDIM*IMOE];

__device__ float g_sgate[T_TOK];
__device__ int   g_top_i[T_TOK*TOPK];
__device__ float g_top_w[T_TOK*TOPK];
__device__ int   g_cnt[NEXP];
__device__ int   g_off[NEXP];
__device__ int   g_fill[NEXP];
__device__ int   g_pair_tok[NPAIR];
__device__ float g_pair_w[NPAIR];

// ---------------- ptx helpers (base sm_103-legal only) ----------------
__device__ __forceinline__ uint32_t smem_u32(const void* p) {
    uint32_t a;
    asm("{ .reg .u64 t; cvta.to.shared.u64 t, %1; cvt.u32.u64 %0, t; }" : "=r"(a) : "l"(p));
    return a;
}
#define LDMX4(r, addr) \
    asm volatile("ldmatrix.sync.aligned.m8n8.x4.shared.b16 {%0,%1,%2,%3}, [%4];" \
        : "=r"((r)[0]), "=r"((r)[1]), "=r"((r)[2]), "=r"((r)[3]) : "r"(addr))
#define MMA_F16(c, a, b0, b1) \
    asm volatile("mma.sync.aligned.m16n8k16.row.col.f32.f16.f16.f32 " \
        "{%0,%1,%2,%3}, {%4,%5,%6,%7}, {%8,%9}, {%0,%1,%2,%3};" \
        : "+f"((c)[0]), "+f"((c)[1]), "+f"((c)[2]), "+f"((c)[3]) \
        : "r"((a)[0]), "r"((a)[1]), "r"((a)[2]), "r"((a)[3]), "r"(b0), "r"(b1))
#define CP_ASYNC16(dst, src) \
    asm volatile("cp.async.cg.shared.global [%0], [%1], 16;" :: "r"(dst), "l"(src))
#define CP_COMMIT() asm volatile("cp.async.commit_group;")
#define CP_WAIT(n)  asm volatile("cp.async.wait_group %0;" :: "n"(n))

// ---------------- loaders (row stride 144B, conflict-free ldmatrix) ----------------
__device__ __forceinline__ void cp_tile64(uint32_t sdst, const __half* g,
                                          int row0, int ld, int k0, int tid) {
    size_t gg = __cvta_generic_to_global(g);
    #pragma unroll
    for (int i = 0; i < 2; i++) {
        int chunk = tid + i*256;
        int row = chunk >> 3, c8 = chunk & 7;
        CP_ASYNC16(sdst + row*144 + c8*16, gg + 2*((size_t)(row0 + row)*ld + k0 + c8*8));
    }
}
__device__ __forceinline__ void cp_tile128(uint32_t sdst, const __half* g,
                                           int row0, int ld, int k0, int tid) {
    size_t gg = __cvta_generic_to_global(g);
    #pragma unroll
    for (int i = 0; i < 4; i++) {
        int chunk = tid + i*256;
        int row = chunk >> 3, c8 = chunk & 7;
        CP_ASYNC16(sdst + row*144 + c8*16, gg + 2*((size_t)(row0 + row)*ld + k0 + c8*8));
    }
}
__device__ __forceinline__ void cp_tile128_clamp(uint32_t sdst, const __half* g,
                                                 int rowadd, int rowmax, int ld, int k0, int tid) {
    size_t gg = __cvta_generic_to_global(g);
    #pragma unroll
    for (int i = 0; i < 4; i++) {
        int chunk = tid + i*256;
        int row = chunk >> 3, c8 = chunk & 7;
        int gr = min(rowadd + row, rowmax);
        CP_ASYNC16(sdst + row*144 + c8*16, gg + 2*((size_t)gr*ld + k0 + c8*8));
    }
}

#define BK 64
#define TILE64   9216           // 64*144
#define TILE128  18432          // 128*144
// gu stage: A (128) + gate (64) + up (64) = 18432 + 2*9216 = 36864; 3 stages
#define STAGE_GU  (TILE128 + 2*TILE64)
#define SMEM_GU   (3*STAGE_GU)              // 110592 -> 2 CTAs/SM
// down stage: A (128) + B (128) = 36864; 3 stages
#define STAGE_DN  (2*TILE128)
#define SMEM_DN   (3*STAGE_DN)              // 110592 -> 2 CTAs/SM

__device__ __forceinline__ float silu_f(float v) { return v / (1.f + expf(-v)); }

// ============ paired gate_up GEMM: BM=128 rows x (64 gate + 64 up) cols ============
// 8 warps, warp tile 32 rows x 32 cols on BOTH gate and up halves.
// wm=(wid>>1)*32 (4 pos), wn=(wid&1)*32 (2 pos). Per kt: 6 LDSM, 16 MMA.
template<bool EXPERT>
__global__ __launch_bounds__(256, 2) void gemm_gu(
    const __half* __restrict__ A,
    const __half* __restrict__ W,
    __half* __restrict__ H,
    int K, int Nhalf)
{
    extern __shared__ char smem[];
    int tid = threadIdx.x;
    int bm = blockIdx.x * 128;
    int cnt = T_TOK, segoff = 0;
    if (EXPERT) {
        int e = blockIdx.z;
        cnt = g_cnt[e]; segoff = g_off[e];
        if (bm >= cnt) return;
        W += (size_t)e * (size_t)(2*Nhalf) * (size_t)K;
    }
    int bn = blockIdx.y * 64;
    uint32_t sbase = smem_u32(smem);
    int rowA = segoff + bm, rowAmax = segoff + cnt - 1;
    int NC = K / BK;

    auto load_stage = [&](int c) {
        uint32_t tb = sbase + (c % 3) * STAGE_GU;
        int k0 = c * BK;
        cp_tile128_clamp(tb, A, rowA, rowAmax, K, k0, tid);
        cp_tile64(tb + TILE128,          W, bn,         K, k0, tid);
        cp_tile64(tb + TILE128 + TILE64, W, Nhalf + bn, K, k0, tid);
        CP_COMMIT();
    };
    load_stage(0);
    if (NC > 1) load_stage(1);

    int lane = tid & 31, wid = tid >> 5;
    int wm = (wid >> 1) * 32, wn = (wid & 1) * 32;
    int lrow = lane & 15;
    int lcolb = (lane >> 4) * 16;

    float accg[2][4][4] = {}, accu[2][4][4] = {};

    for (int c = 0; c < NC; c++) {
        if (c + 2 < NC) { load_stage(c + 2); CP_WAIT(2); }
        else if (c + 1 < NC) { CP_WAIT(1); }
        else { CP_WAIT(0); }
        __syncthreads();

        uint32_t tb = sbase + (c % 3) * STAGE_GU;
        uint32_t sA = tb;
        uint32_t sG = tb + TILE128, sU = tb + TILE128 + TILE64;

        #pragma unroll
        for (int kt = 0; kt < 4; kt++) {
            uint32_t cb = kt*32 + lcolb;
            uint32_t a[2][4];
            #pragma unroll
            for (int mt = 0; mt < 2; mt++)
                LDMX4(a[mt], sA + (uint32_t)(wm + mt*16 + lrow)*144 + cb);
            {
                uint32_t b[2][4];
                #pragma unroll
                for (int p = 0; p < 2; p++)
                    LDMX4(b[p], sG + (uint32_t)(wn + p*16 + lrow)*144 + cb);
                #pragma unroll
                for (int mt = 0; mt < 2; mt++)
                    #pragma unroll
                    for (int nt = 0; nt < 4; nt++) {
                        int p = nt >> 1, s = nt & 1;
                        MMA_F16(accg[mt][nt], a[mt], b[p][s], b[p][s+2]);
                    }
            }
            {
                uint32_t b[2][4];
                #pragma unroll
                for (int p = 0; p < 2; p++)
                    LDMX4(b[p], sU + (uint32_t)(wn + p*16 + lrow)*144 + cb);
                #pragma unroll
                for (int mt = 0; mt < 2; mt++)
                    #pragma unroll
                    for (int nt = 0; nt < 4; nt++) {
                        int p = nt >> 1, s = nt & 1;
                        MMA_F16(accu[mt][nt], a[mt], b[p][s], b[p][s+2]);
                    }
            }
        }
        __syncthreads();
    }

    // fused epilogue: h = silu(g)*u -> fp16, direct store
    int groupID = lane >> 2, qid = lane & 3;
    #pragma unroll
    for (int mt = 0; mt < 2; mt++) {
        #pragma unroll
        for (int half = 0; half < 2; half++) {
            int r = wm + mt*16 + groupID + half*8;
            if (bm + r >= cnt) continue;
            size_t rowoff = (size_t)(segoff + bm + r) * (size_t)Nhalf;
            #pragma unroll
            for (int nt = 0; nt < 4; nt++) {
                int col = bn + wn + nt*8 + qid*2;
                float h0 = silu_f(accg[mt][nt][half*2+0]) * accu[mt][nt][half*2+0];
                float h1 = silu_f(accg[mt][nt][half*2+1]) * accu[mt][nt][half*2+1];
                *(__half2*)&H[rowoff + col] = __halves2half2(__float2half_rn(h0), __float2half_rn(h1));
            }
        }
    }
}

// ============ down GEMM: BM=128 x BN=128, warp tile 64x32 ============
// wm=(wid>>2)*64 (2 pos), wn=(wid&3)*32 (4 pos). Per kt: 6 LDSM, 16 MMA.
// MODE 0: out[row] = sgate[row]*acc (dense write). MODE 1: atomicAdd(out[tok], pair_w*acc)
template<int MODE>
__global__ __launch_bounds__(256, 2) void gemm_down(
    const __half* __restrict__ A,
    const __half* __restrict__ W,
    float* __restrict__ out, int K)
{
    extern __shared__ char smem[];
    int tid = threadIdx.x;
    int bm = blockIdx.x * 128;
    int cnt = T_TOK, segoff = 0;
    if (MODE == 1) {
        int e = blockIdx.z;
        cnt = g_cnt[e]; segoff = g_off[e];
        if (bm >= cnt) return;
        W += (size_t)e * (size_t)HDIM * (size_t)K;
    }
    int bn = blockIdx.y * 128;
    uint32_t sbase = smem_u32(smem);
    int rowA = segoff + bm, rowAmax = segoff + cnt - 1;
    int NC = K / BK;

    auto load_stage = [&](int c) {
        uint32_t tb = sbase + (c % 3) * STAGE_DN;
        int k0 = c * BK;
        cp_tile128_clamp(tb, A, rowA, rowAmax, K, k0, tid);
        cp_tile128(tb + TILE128, W, bn, K, k0, tid);
        CP_COMMIT();
    };
    load_stage(0);
    if (NC > 1) load_stage(1);

    int lane = tid & 31, wid = tid >> 5;
    int wm = (wid >> 2) * 64, wn = (wid & 3) * 32;
    int lrow = lane & 15;
    int lcolb = (lane >> 4) * 16;

    float acc[4][4][4] = {};

    for (int c = 0; c < NC; c++) {
        if (c + 2 < NC) { load_stage(c + 2); CP_WAIT(2); }
        else if (c + 1 < NC) { CP_WAIT(1); }
        else { CP_WAIT(0); }
        __syncthreads();

        uint32_t tb = sbase + (c % 3) * STAGE_DN;
        uint32_t sA = tb;
        uint32_t sB = tb + TILE128;

        #pragma unroll
        for (int kt = 0; kt < 4; kt++) {
            uint32_t cb = kt*32 + lcolb;
            uint32_t a[4][4], b[2][4];
            #pragma unroll
            for (int mt = 0; mt < 4; mt++)
                LDMX4(a[mt], sA + (uint32_t)(wm + mt*16 + lrow)*144 + cb);
            #pragma unroll
            for (int p = 0; p < 2; p++)
                LDMX4(b[p], sB + (uint32_t)(wn + p*16 + lrow)*144 + cb);
            #pragma unroll
            for (int mt = 0; mt < 4; mt++)
                #pragma unroll
                for (int nt = 0; nt < 4; nt++) {
                    int p = nt >> 1, s = nt & 1;
                    MMA_F16(acc[mt][nt], a[mt], b[p][s], b[p][s+2]);
                }
        }
        __syncthreads();
    }

    int groupID = lane >> 2, qid = lane & 3;
    #pragma unroll
    for (int mt = 0; mt < 4; mt++) {
        #pragma unroll
        for (int half = 0; half < 2; half++) {
            int lr = bm + wm + mt*16 + groupID + half*8;
            if (lr >= cnt) continue;
            #pragma unroll
            for (int nt = 0; nt < 4; nt++) {
                int col = bn + wn + nt*8 + qid*2;
                float v0 = acc[mt][nt][half*2 + 0];
                float v1 = acc[mt][nt][half*2 + 1];
                if (MODE == 0) {
                    float s = g_sgate[lr];
                    *(float2*)&out[(size_t)lr*HDIM + col] = make_float2(s*v0, s*v1);
                } else {
                    int p = segoff + lr;
                    int tok = g_pair_tok[p];
                    float w = g_pair_w[p];
                    atomicAdd(&out[(size_t)tok*HDIM + col],     w*v0);
                    atomicAdd(&out[(size_t)tok*HDIM + col + 1], w*v1);
                }
            }
        }
    }
}

// ---------------- conversion kernels ----------------
__global__ void cvt_kernel(const float* __restrict__ src, __half* __restrict__ dst, long n4) {
    long i = blockIdx.x*(long)blockDim.x + threadIdx.x;
    if (i >= n4) return;
    float4 v = ((const float4*)src)[i];
    __half2* D = (__half2*)(dst + 4*i);
    D[0] = __halves2half2(__float2half_rn(v.x), __float2half_rn(v.y));
    D[1] = __halves2half2(__float2half_rn(v.z), __float2half_rn(v.w));
}

__global__ void gather_cvt_kernel(const float* __restrict__ x) {
    int i = blockIdx.x*blockDim.x + threadIdx.x;
    const int n4 = NPAIR * (HDIM/4);
    if (i >= n4) return;
    int p = i / (HDIM/4), c4 = i % (HDIM/4);
    int tok = g_pair_tok[p];
    float4 v = *(const float4*)(x + (size_t)tok*HDIM + c4*4);
    size_t o = (size_t)p*HDIM + c4*4;
    ((__half2*)(g_xg + o))[0] = __halves2half2(__float2half_rn(v.x), __float2half_rn(v.y));
    ((__half2*)(g_xg + o))[1] = __halves2half2(__float2half_rn(v.z), __float2half_rn(v.w));
}

// ---------------- router ----------------
__global__ void zero_kernel() {
    int i = threadIdx.x;
    if (i < NEXP) { g_cnt[i] = 0; g_fill[i] = 0; }
}
__global__ void router_kernel(const float* __restrict__ x,
                              const float* __restrict__ gate_w,
                              const float* __restrict__ sgate_w) {
    int t = blockIdx.x;
    int w = threadIdx.x >> 5, lane = threadIdx.x & 31;
    __shared__ float logits[9];
    const float* xr = x + (size_t)t * HDIM;
    const float* wr = (w < 8) ? (gate_w + (size_t)w * HDIM) : sgate_w;
    float s = 0.f;
    for (int k = lane; k < HDIM; k += 32) s += xr[k] * wr[k];
    #pragma unroll
    for (int o = 16; o; o >>= 1) s += __shfl_xor_sync(0xffffffffu, s, o);
    if (lane == 0) logits[w] = s;
    __syncthreads();
    if (threadIdx.x == 0) {
        float mx = logits[0];
        #pragma unroll
        for (int e = 1; e < NEXP; e++) mx = fmaxf(mx, logits[e]);
        float p[NEXP], sum = 0.f;
        #pragma unroll
        for (int e = 0; e < NEXP; e++) { p[e] = expf(logits[e] - mx); sum += p[e]; }
        #pragma unroll
        for (int e = 0; e < NEXP; e++) p[e] /= sum;
        int i0 = 0; float v0 = p[0];
        #pragma unroll
        for (int e = 1; e < NEXP; e++) if (p[e] > v0) { v0 = p[e]; i0 = e; }
        int i1 = -1; float v1 = -1.f;
        #pragma unroll
        for (int e = 0; e < NEXP; e++) if (e != i0 && p[e] > v1) { v1 = p[e]; i1 = e; }
        float inv = 1.f / (v0 + v1);
        g_top_i[t*2+0] = i0; g_top_w[t*2+0] = v0 * inv;
        g_top_i[t*2+1] = i1; g_top_w[t*2+1] = v1 * inv;
        atomicAdd(&g_cnt[i0], 1);
        atomicAdd(&g_cnt[i1], 1);
        g_sgate[t] = 1.f / (1.f + expf(-logits[8]));
    }
}
__global__ void scan_kernel() {
    if (threadIdx.x == 0) {
        int o = 0;
        for (int e = 0; e < NEXP; e++) { g_off[e] = o; o += g_cnt[e]; }
    }
}
__global__ void scatter_kernel() {
    int t = blockIdx.x * blockDim.x + threadIdx.x;
    if (t >= T_TOK) return;
    #pragma unroll
    for (int k = 0; k < TOPK; k++) {
        int e = g_top_i[t*2+k];
        int pos = g_off[e] + atomicAdd(&g_fill[e], 1);
        g_pair_tok[pos] = t;
        g_pair_w[pos]   = g_top_w[t*2+k];
    }
}

// ---------------- launch (R10 schedule verbatim) ----------------
static void* sym(const void* s) { void* p = nullptr; cudaGetSymbolAddress(&p, s); return p; }

extern "C" void kernel_launch(void* const* d_in, const int* in_sizes, int n_in,
                              void* d_out, int out_size) {
    const float* x     = (const float*)d_in[0];
    const float* gatew = (const float*)d_in[1];
    const float* w1    = (const float*)d_in[2];
    const float* w2    = (const float*)d_in[3];
    const float* sgu   = (const float*)d_in[4];
    const float* sdown = (const float*)d_in[5];
    const float* sgw   = (const float*)d_in[6];
    float* out = (float*)d_out;

    cudaFuncSetAttribute(gemm_gu<false>, cudaFuncAttributeMaxDynamicSharedMemorySize, SMEM_GU);
    cudaFuncSetAttribute(gemm_gu<true>,  cudaFuncAttributeMaxDynamicSharedMemorySize, SMEM_GU);
    cudaFuncSetAttribute(gemm_down<0>,   cudaFuncAttributeMaxDynamicSharedMemorySize, SMEM_DN);
    cudaFuncSetAttribute(gemm_down<1>,   cudaFuncAttributeMaxDynamicSharedMemorySize, SMEM_DN);

    __half *xh  = (__half*)sym(g_x);
    __half *hsh = (__half*)sym(g_hsh);
    __half *xgh = (__half*)sym(g_xg);
    __half *heh = (__half*)sym(g_he);
    __half *wsgu= (__half*)sym(g_wsgu);
    __half *wsdn= (__half*)sym(g_wsdn);
    __half *w1h = (__half*)sym(g_w1);
    __half *w2h = (__half*)sym(g_w2);

    cudaStream_t s2;
    cudaEvent_t e_fork, e_join;
    cudaStreamCreateWithFlags(&s2, cudaStreamNonBlocking);
    cudaEventCreateWithFlags(&e_fork, cudaEventDisableTiming);
    cudaEventCreateWithFlags(&e_join, cudaEventDisableTiming);

    cudaEventRecord(e_fork, 0);
    cudaStreamWaitEvent(s2, e_fork, 0);

    auto cvt = [](cudaStream_t st, const float* s, __half* d, long n) {
        long n4 = n / 4;
        cvt_kernel<<<(unsigned)((n4 + 255) / 256), 256, 0, st>>>(s, d, n4);
    };

    // --- s2: expert chain: router + scatter + gathered x cvt + weight cvts -> expert gu ---
    zero_kernel<<<1, 32, 0, s2>>>();
    router_kernel<<<T_TOK, 288, 0, s2>>>(x, gatew, sgw);
    scan_kernel<<<1, 32, 0, s2>>>();
    scatter_kernel<<<(T_TOK + 255) / 256, 256, 0, s2>>>();
    gather_cvt_kernel<<<(NPAIR*(HDIM/4) + 255) / 256, 256, 0, s2>>>(x);
    cvt(s2, w1, w1h, (long)NEXP*2*IMOE*HDIM);
    cvt(s2, w2, w2h, (long)NEXP*HDIM*IMOE);
    gemm_gu<true><<<dim3(T_TOK/128, IMOE/64, NEXP), 256, SMEM_GU, s2>>>(
        xgh, w1h, heh, HDIM, IMOE);

    // --- default stream: shared expert chain ---
    cvt(0, x, xh, (long)T_TOK*HDIM);
    cvt(0, sgu, wsgu, (long)2*ISH*HDIM);
    cvt(0, sdown, wsdn, (long)HDIM*ISH);
    gemm_gu<false><<<dim3(T_TOK/128, ISH/64), 256, SMEM_GU>>>(
        xh, wsgu, hsh, HDIM, ISH);
    gemm_down<0><<<dim3(T_TOK/128, HDIM/128), 256, SMEM_DN>>>(
        hsh, wsdn, out, ISH);

    // join: expert down needs both chains
    cudaEventRecord(e_join, s2);
    cudaStreamWaitEvent(0, e_join, 0);
    gemm_down<1><<<dim3(T_TOK/128, HDIM/128, NEXP), 256, SMEM_DN>>>(
        heh, w2h, out, IMOE);

    cudaEventDestroy(e_fork);
    cudaEventDestroy(e_join);
    cudaStreamDestroy(s2);
}